// round 3
// baseline (speedup 1.0000x reference)
#include <cuda_runtime.h>
#include <cstdint>

// ---------------- problem constants ----------------
#define BATCH   16
#define SEQ     2048
#define INP     256
#define HID     1024
#define MAXNZ   64
#define NCTA    128
#define NTHR    256
#define OUT_MAIN (BATCH*SEQ*INP)        // 8388608
#define HT_ELEMS (2*BATCH*HID)          // 32768
#define SQRT10  3.1622776601683795f

// ---------------- device scratch (no allocs allowed) ----------------
__device__ float          g_xT[(size_t)SEQ*INP*BATCH];       // [t][j][b]  33.5MB
__device__ float          g_outsT[(size_t)SEQ*HID*BATCH];    // [t][i][b]  134MB (h1 per step)
__device__ float          g_h0[2][HID*BATCH];                // ping-pong layer0 state
__device__ float          g_WT[HID*INP];                     // out_w transposed [i][o]
__device__ unsigned short g_idx[3][HID][MAXNZ];              // 0: ih0, 1: hh0, 2: hh1
__device__ float          g_val[3][HID][MAXNZ];
__device__ int            g_cnt[3][HID];
__device__ unsigned int   g_slots[NCTA];

// ---------------- small helpers ----------------
__device__ __forceinline__ unsigned long long pk2(float lo, float hi) {
    unsigned long long r;
    asm("mov.b64 %0, {%1,%2};" : "=l"(r) : "f"(lo), "f"(hi));
    return r;
}
__device__ __forceinline__ void upk2(unsigned long long v, float& lo, float& hi) {
    asm("mov.b64 {%0,%1}, %2;" : "=f"(lo), "=f"(hi) : "l"(v));
}
__device__ __forceinline__ void fma2(unsigned long long& d, unsigned long long a, unsigned long long b) {
    asm("fma.rn.f32x2 %0, %1, %2, %3;" : "=l"(d) : "l"(a), "l"(b), "l"(d));
}

// ---------------- kernel: zero barrier slots ----------------
__global__ void k_zero_slots() {
    if (threadIdx.x < NCTA) g_slots[threadIdx.x] = 0u;
}

// ---------------- kernel: transpose x [b][t][j] -> xT [t][j][b] ----------------
__global__ void k_xT(const float* __restrict__ x) {
    __shared__ float sm[INP * 17];
    int t = blockIdx.x;
    int tid = threadIdx.x;   // 256 threads; tid == j on load
    #pragma unroll
    for (int bb = 0; bb < BATCH; bb++) {
        sm[tid * 17 + bb] = x[(size_t)bb * SEQ * INP + (size_t)t * INP + tid];
    }
    __syncthreads();
    float* dst = g_xT + (size_t)t * (INP * BATCH);
    #pragma unroll
    for (int k = 0; k < 16; k++) {
        int f = k * 256 + tid;            // f = j*16 + b
        dst[f] = sm[(f >> 4) * 17 + (f & 15)];
    }
}

// ---------------- kernel: build CSR for the 3 sparse matrices ----------------
// m=0: weight_ih[0]  (1024 x 256)
// m=1: weight_hh[0]  (1024 x 1024)
// m=2: weight_hh[1]  (1024 x 1024)
__global__ void k_csr(const float* __restrict__ wih, const float* __restrict__ whh) {
    int warp = threadIdx.x >> 5;
    int lane = threadIdx.x & 31;
    int gr = blockIdx.x * 8 + warp;        // 0..3071
    if (gr >= 3 * HID) return;
    int m = gr / HID;
    int row = gr % HID;
    const float* src;
    int ncol;
    if (m == 0) { src = wih + (size_t)row * INP; ncol = INP; }
    else        { src = whh + ((size_t)(m - 1) * HID + row) * HID; ncol = HID; }
    int base = 0;
    for (int c0 = 0; c0 < ncol; c0 += 32) {
        float w = src[c0 + lane];
        unsigned mask = __ballot_sync(0xffffffffu, w != 0.0f);
        if (w != 0.0f) {
            int pos = base + __popc(mask & ((1u << lane) - 1u));
            if (pos < MAXNZ) {
                g_idx[m][row][pos] = (unsigned short)(c0 + lane);
                g_val[m][row][pos] = w;
            }
        }
        base += __popc(mask);
    }
    int cnt = base < MAXNZ ? base : MAXNZ;
    int rcnt = (cnt + 3) & ~3;             // pad to multiple of 4 with zeros
    for (int p = cnt + lane; p < rcnt; p += 32) {
        g_idx[m][row][p] = 0;
        g_val[m][row][p] = 0.0f;
    }
    if (lane == 0) g_cnt[m][row] = rcnt;
}

// ---------------- kernel: transpose out_w [o][i] -> WT [i][o] ----------------
__global__ void k_wT(const float* __restrict__ ow) {
    __shared__ float tl[32][33];
    int i0 = blockIdx.x * 32, o0 = blockIdx.y * 32;
    int tx = threadIdx.x, ty = threadIdx.y;
    tl[ty][tx] = ow[(size_t)(o0 + ty) * HID + i0 + tx];
    __syncthreads();
    g_WT[(size_t)(i0 + ty) * INP + o0 + tx] = tl[tx][ty];
}

// ---------------- grid barrier (slot array, release/acquire) ----------------
__device__ __forceinline__ void gridbar(int p) {
    __syncthreads();
    if (threadIdx.x == 0) {
        __threadfence();
        asm volatile("st.release.gpu.global.u32 [%0], %1;"
                     :: "l"(g_slots + blockIdx.x), "r"((unsigned)(p + 1)) : "memory");
    }
    if (threadIdx.x < 32) {
        unsigned target = (unsigned)(p + 1);
        int l = threadIdx.x;
        for (;;) {
            unsigned v0, v1, v2, v3;
            asm volatile("ld.acquire.gpu.global.u32 %0, [%1];" : "=r"(v0) : "l"(g_slots + l)      : "memory");
            asm volatile("ld.acquire.gpu.global.u32 %0, [%1];" : "=r"(v1) : "l"(g_slots + l + 32) : "memory");
            asm volatile("ld.acquire.gpu.global.u32 %0, [%1];" : "=r"(v2) : "l"(g_slots + l + 64) : "memory");
            asm volatile("ld.acquire.gpu.global.u32 %0, [%1];" : "=r"(v3) : "l"(g_slots + l + 96) : "memory");
            bool ok = (v0 >= target) && (v1 >= target) && (v2 >= target) && (v3 >= target);
            if (__all_sync(0xffffffffu, ok)) break;
        }
    }
    __syncthreads();
}

// ---------------- persistent recurrence kernel ----------------
// CTAs 0..63  : layer 0, neurons [cta*16, cta*16+16)
// CTAs 64..127: layer 1, neurons [(cta-64)*16, ...)
// phase p: layer0 computes step t=p (p<SEQ); layer1 computes step t=p-1 (p>=1)
__global__ void __launch_bounds__(NTHR, 1) k_rnn() {
    __shared__ unsigned short sIdxA[16][MAXNZ];
    __shared__ float          sValA[16][MAXNZ];
    __shared__ unsigned short sIdxB[16][MAXNZ];
    __shared__ float          sValB[16][MAXNZ];
    __shared__ int sCntA[16], sCntB[16];

    int cta = blockIdx.x;
    int layer = cta >> 6;
    int r0 = (cta & 63) * 16;
    int mA = (layer == 0) ? 0 : 2;

    for (int e = threadIdx.x; e < 16 * MAXNZ; e += NTHR) {
        int rr = e >> 6, kk = e & 63;
        sIdxA[rr][kk] = g_idx[mA][r0 + rr][kk];
        sValA[rr][kk] = g_val[mA][r0 + rr][kk];
        if (layer == 0) {
            sIdxB[rr][kk] = g_idx[1][r0 + rr][kk];
            sValB[rr][kk] = g_val[1][r0 + rr][kk];
        }
    }
    if (threadIdx.x < 16) {
        sCntA[threadIdx.x] = g_cnt[mA][r0 + threadIdx.x];
        sCntB[threadIdx.x] = (layer == 0) ? g_cnt[1][r0 + threadIdx.x] : 0;
    }
    __syncthreads();

    int warp = threadIdx.x >> 5;
    int lane = threadIdx.x & 31;
    int il = 2 * warp + (lane >> 4);   // local neuron 0..15
    int b  = lane & 15;                // batch
    int i  = r0 + il;
    int cA = sCntA[il];
    int cB = sCntB[il];

    for (int p = 0; p <= SEQ; p++) {
        if (layer == 0) {
            if (p < SEQ) {
                int t = p;
                float acc0 = SQRT10, acc1 = 0.0f;
                const float* xp = g_xT + (size_t)t * (INP * BATCH) + b;
                for (int k = 0; k < cA; k += 4) {
                    int j0 = sIdxA[il][k], j1 = sIdxA[il][k + 1], j2 = sIdxA[il][k + 2], j3 = sIdxA[il][k + 3];
                    float v0 = sValA[il][k], v1 = sValA[il][k + 1], v2 = sValA[il][k + 2], v3 = sValA[il][k + 3];
                    acc0 += v0 * __ldg(xp + (j0 << 4));
                    acc1 += v1 * __ldg(xp + (j1 << 4));
                    acc0 += v2 * __ldg(xp + (j2 << 4));
                    acc1 += v3 * __ldg(xp + (j3 << 4));
                }
                if (t > 0) {
                    const float* hp = g_h0[(p + 1) & 1] + b;
                    for (int k = 0; k < cB; k += 4) {
                        int j0 = sIdxB[il][k], j1 = sIdxB[il][k + 1], j2 = sIdxB[il][k + 2], j3 = sIdxB[il][k + 3];
                        float v0 = sValB[il][k], v1 = sValB[il][k + 1], v2 = sValB[il][k + 2], v3 = sValB[il][k + 3];
                        acc0 += v0 * __ldcg(hp + (j0 << 4));
                        acc1 += v1 * __ldcg(hp + (j1 << 4));
                        acc0 += v2 * __ldcg(hp + (j2 << 4));
                        acc1 += v3 * __ldcg(hp + (j3 << 4));
                    }
                }
                __stcg(&g_h0[p & 1][i * 16 + b], fmaxf(acc0 + acc1, 0.0f));
            }
        } else {
            if (p >= 1) {
                int t = p - 1;
                float acc0 = SQRT10, acc1 = 0.0f;
                const float* h0c = g_h0[(p + 1) & 1] + b;
                if (t > 0) {
                    const float* h1p = g_outsT + (size_t)(t - 1) * (HID * BATCH) + b;
                    for (int k = 0; k < cA; k += 4) {
                        int j0 = sIdxA[il][k], j1 = sIdxA[il][k + 1], j2 = sIdxA[il][k + 2], j3 = sIdxA[il][k + 3];
                        float v0 = sValA[il][k], v1 = sValA[il][k + 1], v2 = sValA[il][k + 2], v3 = sValA[il][k + 3];
                        float s0 = __ldcg(h0c + (j0 << 4)) + __ldcg(h1p + (j0 << 4));
                        float s1 = __ldcg(h0c + (j1 << 4)) + __ldcg(h1p + (j1 << 4));
                        float s2 = __ldcg(h0c + (j2 << 4)) + __ldcg(h1p + (j2 << 4));
                        float s3 = __ldcg(h0c + (j3 << 4)) + __ldcg(h1p + (j3 << 4));
                        acc0 += v0 * s0;
                        acc1 += v1 * s1;
                        acc0 += v2 * s2;
                        acc1 += v3 * s3;
                    }
                } else {
                    for (int k = 0; k < cA; k += 4) {
                        int j0 = sIdxA[il][k], j1 = sIdxA[il][k + 1], j2 = sIdxA[il][k + 2], j3 = sIdxA[il][k + 3];
                        float v0 = sValA[il][k], v1 = sValA[il][k + 1], v2 = sValA[il][k + 2], v3 = sValA[il][k + 3];
                        acc0 += v0 * __ldcg(h0c + (j0 << 4));
                        acc1 += v1 * __ldcg(h0c + (j1 << 4));
                        acc0 += v2 * __ldcg(h0c + (j2 << 4));
                        acc1 += v3 * __ldcg(h0c + (j3 << 4));
                    }
                }
                __stcg(&g_outsT[(size_t)t * (HID * BATCH) + i * 16 + b], fmaxf(acc0 + acc1, 0.0f));
            }
        }
        gridbar(p);
    }
}

// ---------------- projection: out[b][t][o] = sum_i h1[t][i][b]*W[o][i] + bias[o] ----------------
__global__ void __launch_bounds__(NTHR) k_proj(const float* __restrict__ ob, float* __restrict__ out) {
    __shared__ float sh[512 * BATCH];    // 32KB, half of one timestep's h1
    int t = blockIdx.x;
    int o = threadIdx.x;
    float bias = __ldg(ob + o);
    unsigned long long acc[8];
    #pragma unroll
    for (int j = 0; j < 8; j++) acc[j] = pk2(bias, bias);
    // bias added once per slot is wrong if repeated — it is set once here, then only FMA accumulates.
    #pragma unroll
    for (int half = 0; half < 2; half++) {
        __syncthreads();
        const float* src = g_outsT + (size_t)t * (HID * BATCH) + half * (512 * BATCH);
        for (int e = threadIdx.x; e < 512 * BATCH; e += NTHR) sh[e] = src[e];
        __syncthreads();
        const float* wcol = g_WT + (size_t)(half * 512) * INP + o;
        #pragma unroll 2
        for (int i = 0; i < 512; i++) {
            float w = __ldg(wcol + (size_t)i * INP);
            unsigned long long wp = pk2(w, w);
            const unsigned long long* hp = (const unsigned long long*)(sh + i * BATCH);
            fma2(acc[0], hp[0], wp);
            fma2(acc[1], hp[1], wp);
            fma2(acc[2], hp[2], wp);
            fma2(acc[3], hp[3], wp);
            fma2(acc[4], hp[4], wp);
            fma2(acc[5], hp[5], wp);
            fma2(acc[6], hp[6], wp);
            fma2(acc[7], hp[7], wp);
        }
    }
    #pragma unroll
    for (int j = 0; j < 8; j++) {
        float lo, hi;
        upk2(acc[j], lo, hi);
        out[((size_t)(2 * j)     * SEQ + t) * INP + o] = lo;
        out[((size_t)(2 * j + 1) * SEQ + t) * INP + o] = hi;
    }
}

// ---------------- final hidden state h_T [l][b][i] ----------------
__global__ void k_ht(float* __restrict__ out) {
    int e = blockIdx.x * blockDim.x + threadIdx.x;
    if (e >= HT_ELEMS) return;
    int l = e / (BATCH * HID);
    int r = e % (BATCH * HID);
    int b = r / HID;
    int i = r % HID;
    float v;
    if (l == 0) v = g_h0[(SEQ - 1) & 1][i * 16 + b];
    else        v = g_outsT[(size_t)(SEQ - 1) * (HID * BATCH) + i * 16 + b];
    out[(size_t)OUT_MAIN + e] = v;
}

// ---------------- launch ----------------
extern "C" void kernel_launch(void* const* d_in, const int* in_sizes, int n_in,
                              void* d_out, int out_size) {
    const float* x   = (const float*)d_in[0];
    const float* wih = (const float*)d_in[1];
    const float* whh = (const float*)d_in[2];
    const float* ow  = (const float*)d_in[3];
    const float* ob  = (const float*)d_in[4];
    float* out = (float*)d_out;

    k_zero_slots<<<1, 128>>>();
    k_xT<<<SEQ, 256>>>(x);
    k_csr<<<(3 * HID) / 8, 256>>>(wih, whh);
    k_wT<<<dim3(HID / 32, INP / 32), dim3(32, 32)>>>(ow);
    k_rnn<<<NCTA, NTHR>>>();
    k_proj<<<SEQ, NTHR>>>(ob, out);
    if (out_size >= OUT_MAIN + HT_ELEMS) {
        k_ht<<<(HT_ELEMS + 511) / 512, 512>>>(out);
    }
}

// round 6
// speedup vs baseline: 1.2361x; 1.2361x over previous
#include <cuda_runtime.h>
#include <cstdint>

// ---------------- problem constants ----------------
#define BATCH   16
#define SEQ     2048
#define INP     256
#define HID     1024
#define MAXNZ   64
#define NCTA    128
#define NTHR    256
#define HDEPTH  4                        // h0 ping-pong depth (layer0 may run ahead)
#define OUT_MAIN (BATCH*SEQ*INP)        // 8388608
#define HT_ELEMS (2*BATCH*HID)          // 32768
#define SQRT10  3.1622776601683795f

// ---------------- device scratch (no allocs allowed) ----------------
__device__ float          g_xT[(size_t)SEQ*INP*BATCH];       // [t][j][b]
__device__ float          g_outsT[(size_t)SEQ*HID*BATCH];    // [t][i][b]  (h1 per step)
__device__ float          g_h0[HDEPTH][HID*BATCH];           // layer0 state ring
__device__ float          g_WT[HID*INP];                     // out_w transposed [i][o]
__device__ unsigned short g_idx[3][HID][MAXNZ];              // 0: ih0, 1: hh0, 2: hh1
__device__ float          g_val[3][HID][MAXNZ];
__device__ int            g_cnt[3][HID];

struct __align__(128) Ctr { unsigned v; unsigned pad[31]; };
__device__ Ctr g_ctr[2];                 // [0]=layer0 arrivals, [1]=layer1 arrivals

// ---------------- small helpers ----------------
__device__ __forceinline__ unsigned long long pk2(float lo, float hi) {
    unsigned long long r;
    asm("mov.b64 %0, {%1,%2};" : "=l"(r) : "f"(lo), "f"(hi));
    return r;
}
__device__ __forceinline__ void upk2(unsigned long long v, float& lo, float& hi) {
    asm("mov.b64 {%0,%1}, %2;" : "=f"(lo), "=f"(hi) : "l"(v));
}
__device__ __forceinline__ void fma2(unsigned long long& d, unsigned long long a, unsigned long long b) {
    asm("fma.rn.f32x2 %0, %1, %2, %3;" : "=l"(d) : "l"(a), "l"(b), "l"(d));
}
__device__ __forceinline__ void red_release(unsigned* p) {
    asm volatile("red.release.gpu.global.add.u32 [%0], %1;" :: "l"(p), "r"(1u) : "memory");
}
__device__ __forceinline__ unsigned ld_acq(const unsigned* p) {
    unsigned v;
    asm volatile("ld.acquire.gpu.global.u32 %0, [%1];" : "=r"(v) : "l"(p) : "memory");
    return v;
}
// spin until *p >= tgt (call from warp 0, warp-uniform)
__device__ __forceinline__ void spin_ge(const unsigned* p, unsigned tgt) {
    while (ld_acq(p) < tgt) { }
}

// ---------------- kernel: zero counters ----------------
__global__ void k_zero_slots() {
    if (threadIdx.x < 2) g_ctr[threadIdx.x].v = 0u;
}

// ---------------- kernel: transpose x [b][t][j] -> xT [t][j][b] ----------------
__global__ void k_xT(const float* __restrict__ x) {
    __shared__ float sm[INP * 17];
    int t = blockIdx.x;
    int tid = threadIdx.x;
    #pragma unroll
    for (int bb = 0; bb < BATCH; bb++) {
        sm[tid * 17 + bb] = x[(size_t)bb * SEQ * INP + (size_t)t * INP + tid];
    }
    __syncthreads();
    float* dst = g_xT + (size_t)t * (INP * BATCH);
    #pragma unroll
    for (int k = 0; k < 16; k++) {
        int f = k * 256 + tid;            // f = j*16 + b
        dst[f] = sm[(f >> 4) * 17 + (f & 15)];
    }
}

// ---------------- kernel: build CSR ----------------
__global__ void k_csr(const float* __restrict__ wih, const float* __restrict__ whh) {
    int warp = threadIdx.x >> 5;
    int lane = threadIdx.x & 31;
    int gr = blockIdx.x * 8 + warp;
    if (gr >= 3 * HID) return;
    int m = gr / HID;
    int row = gr % HID;
    const float* src;
    int ncol;
    if (m == 0) { src = wih + (size_t)row * INP; ncol = INP; }
    else        { src = whh + ((size_t)(m - 1) * HID + row) * HID; ncol = HID; }
    int base = 0;
    for (int c0 = 0; c0 < ncol; c0 += 32) {
        float w = src[c0 + lane];
        unsigned mask = __ballot_sync(0xffffffffu, w != 0.0f);
        if (w != 0.0f) {
            int pos = base + __popc(mask & ((1u << lane) - 1u));
            if (pos < MAXNZ) {
                g_idx[m][row][pos] = (unsigned short)(c0 + lane);
                g_val[m][row][pos] = w;
            }
        }
        base += __popc(mask);
    }
    int cnt = base < MAXNZ ? base : MAXNZ;
    int rcnt = (cnt + 3) & ~3;
    for (int p = cnt + lane; p < rcnt; p += 32) {
        g_idx[m][row][p] = 0;
        g_val[m][row][p] = 0.0f;
    }
    if (lane == 0) g_cnt[m][row] = rcnt;
}

// ---------------- kernel: transpose out_w ----------------
__global__ void k_wT(const float* __restrict__ ow) {
    __shared__ float tl[32][33];
    int i0 = blockIdx.x * 32, o0 = blockIdx.y * 32;
    int tx = threadIdx.x, ty = threadIdx.y;
    tl[ty][tx] = ow[(size_t)(o0 + ty) * HID + i0 + tx];
    __syncthreads();
    g_WT[(size_t)(i0 + ty) * INP + o0 + tx] = tl[tx][ty];
}

// ---------------- persistent recurrence kernel ----------------
// CTAs 0..63  : layer 0, neurons [cta*16, cta*16+16)
// CTAs 64..127: layer 1
// Two independent 64-CTA counter barriers; layer1 chases layer0.
__global__ void __launch_bounds__(NTHR, 1) k_rnn() {
    __shared__ unsigned short sIdxA[16][MAXNZ];
    __shared__ float          sValA[16][MAXNZ];
    __shared__ unsigned short sIdxB[16][MAXNZ];
    __shared__ float          sValB[16][MAXNZ];
    __shared__ int sCntA[16], sCntB[16];

    int cta = blockIdx.x;
    int layer = cta >> 6;
    int r0 = (cta & 63) * 16;
    int mA = (layer == 0) ? 0 : 2;       // layer0: ih0 ; layer1: hh1

    for (int e = threadIdx.x; e < 16 * MAXNZ; e += NTHR) {
        int rr = e >> 6, kk = e & 63;
        sIdxA[rr][kk] = g_idx[mA][r0 + rr][kk];
        sValA[rr][kk] = g_val[mA][r0 + rr][kk];
        if (layer == 0) {
            sIdxB[rr][kk] = g_idx[1][r0 + rr][kk];   // hh0
            sValB[rr][kk] = g_val[1][r0 + rr][kk];
        }
    }
    if (threadIdx.x < 16) {
        sCntA[threadIdx.x] = g_cnt[mA][r0 + threadIdx.x];
        sCntB[threadIdx.x] = (layer == 0) ? g_cnt[1][r0 + threadIdx.x] : 0;
    }
    __syncthreads();

    int warp = threadIdx.x >> 5;
    int lane = threadIdx.x & 31;
    int il = 2 * warp + (lane >> 4);   // local neuron 0..15
    int b  = lane & 15;                // batch
    int i  = r0 + il;
    int cA = sCntA[il];
    int cB = sCntB[il];

    if (layer == 0) {
        // ---------------- layer 0 pipeline ----------------
        // prefetch ffx(0)
        float ffx;
        {
            const float* xp = g_xT + b;
            float a0 = 0.0f, a1 = 0.0f;
            for (int k = 0; k < cA; k += 4) {
                int j0 = sIdxA[il][k], j1 = sIdxA[il][k+1], j2 = sIdxA[il][k+2], j3 = sIdxA[il][k+3];
                float v0 = sValA[il][k], v1 = sValA[il][k+1], v2 = sValA[il][k+2], v3 = sValA[il][k+3];
                a0 += v0 * __ldg(xp + (j0 << 4));
                a1 += v1 * __ldg(xp + (j1 << 4));
                a0 += v2 * __ldg(xp + (j2 << 4));
                a1 += v3 * __ldg(xp + (j3 << 4));
            }
            ffx = a0 + a1;
        }
        for (int t = 0; t < SEQ; t++) {
            if (t > 0) {
                if (threadIdx.x < 32) {
                    spin_ge(&g_ctr[0].v, 64u * (unsigned)t);         // all h0(t-1) visible
                    if (t >= HDEPTH)
                        spin_ge(&g_ctr[1].v, 64u * (unsigned)(t - HDEPTH + 1)); // ring slot free
                }
                __syncthreads();
            }
            float acc0 = SQRT10 + ffx, acc1 = 0.0f;
            if (t > 0) {
                const float* hp = g_h0[(t - 1) & (HDEPTH - 1)] + b;
                for (int k = 0; k < cB; k += 4) {
                    int j0 = sIdxB[il][k], j1 = sIdxB[il][k+1], j2 = sIdxB[il][k+2], j3 = sIdxB[il][k+3];
                    float v0 = sValB[il][k], v1 = sValB[il][k+1], v2 = sValB[il][k+2], v3 = sValB[il][k+3];
                    acc0 += v0 * __ldcg(hp + (j0 << 4));
                    acc1 += v1 * __ldcg(hp + (j1 << 4));
                    acc0 += v2 * __ldcg(hp + (j2 << 4));
                    acc1 += v3 * __ldcg(hp + (j3 << 4));
                }
            }
            __stcg(&g_h0[t & (HDEPTH - 1)][i * 16 + b], fmaxf(acc0 + acc1, 0.0f));
            __syncthreads();
            if (threadIdx.x == 0) red_release(&g_ctr[0].v);
            // prefetch ffx(t+1) AFTER release -> x DRAM latency off critical path
            if (t + 1 < SEQ) {
                const float* xp = g_xT + (size_t)(t + 1) * (INP * BATCH) + b;
                float a0 = 0.0f, a1 = 0.0f;
                for (int k = 0; k < cA; k += 4) {
                    int j0 = sIdxA[il][k], j1 = sIdxA[il][k+1], j2 = sIdxA[il][k+2], j3 = sIdxA[il][k+3];
                    float v0 = sValA[il][k], v1 = sValA[il][k+1], v2 = sValA[il][k+2], v3 = sValA[il][k+3];
                    a0 += v0 * __ldg(xp + (j0 << 4));
                    a1 += v1 * __ldg(xp + (j1 << 4));
                    a0 += v2 * __ldg(xp + (j2 << 4));
                    a1 += v3 * __ldg(xp + (j3 << 4));
                }
                ffx = a0 + a1;
            }
        }
    } else {
        // ---------------- layer 1 pipeline ----------------
        for (int t = 0; t < SEQ; t++) {
            float accR0 = 0.0f, accR1 = 0.0f;
            if (t > 0) {
                if (threadIdx.x < 32) spin_ge(&g_ctr[1].v, 64u * (unsigned)t);  // h1(t-1) visible
                __syncthreads();
                // gather recurrence while layer0 may still be finishing h0(t)
                const float* hp = g_outsT + (size_t)(t - 1) * (HID * BATCH) + b;
                for (int k = 0; k < cA; k += 4) {
                    int j0 = sIdxA[il][k], j1 = sIdxA[il][k+1], j2 = sIdxA[il][k+2], j3 = sIdxA[il][k+3];
                    float v0 = sValA[il][k], v1 = sValA[il][k+1], v2 = sValA[il][k+2], v3 = sValA[il][k+3];
                    accR0 += v0 * __ldcg(hp + (j0 << 4));
                    accR1 += v1 * __ldcg(hp + (j1 << 4));
                    accR0 += v2 * __ldcg(hp + (j2 << 4));
                    accR1 += v3 * __ldcg(hp + (j3 << 4));
                }
            }
            if (threadIdx.x < 32) spin_ge(&g_ctr[0].v, 64u * (unsigned)(t + 1)); // h0(t) visible
            __syncthreads();
            float acc0 = SQRT10 + accR0, acc1 = accR1;
            {
                const float* fp = g_h0[t & (HDEPTH - 1)] + b;
                for (int k = 0; k < cA; k += 4) {
                    int j0 = sIdxA[il][k], j1 = sIdxA[il][k+1], j2 = sIdxA[il][k+2], j3 = sIdxA[il][k+3];
                    float v0 = sValA[il][k], v1 = sValA[il][k+1], v2 = sValA[il][k+2], v3 = sValA[il][k+3];
                    acc0 += v0 * __ldcg(fp + (j0 << 4));
                    acc1 += v1 * __ldcg(fp + (j1 << 4));
                    acc0 += v2 * __ldcg(fp + (j2 << 4));
                    acc1 += v3 * __ldcg(fp + (j3 << 4));
                }
            }
            __stcg(&g_outsT[(size_t)t * (HID * BATCH) + i * 16 + b], fmaxf(acc0 + acc1, 0.0f));
            __syncthreads();
            if (threadIdx.x == 0) red_release(&g_ctr[1].v);
        }
    }
}

// ---------------- projection: out[b][t][o] = sum_i h1[t][i][b]*W[o][i] + bias[o] ----------------
__global__ void __launch_bounds__(NTHR) k_proj(const float* __restrict__ ob, float* __restrict__ out) {
    __shared__ float sh[512 * BATCH];
    int t = blockIdx.x;
    int o = threadIdx.x;
    float bias = __ldg(ob + o);
    unsigned long long acc[8];
    #pragma unroll
    for (int j = 0; j < 8; j++) acc[j] = pk2(bias, bias);
    #pragma unroll
    for (int half = 0; half < 2; half++) {
        __syncthreads();
        const float* src = g_outsT + (size_t)t * (HID * BATCH) + half * (512 * BATCH);
        for (int e = threadIdx.x; e < 512 * BATCH; e += NTHR) sh[e] = src[e];
        __syncthreads();
        const float* wcol = g_WT + (size_t)(half * 512) * INP + o;
        #pragma unroll 2
        for (int i = 0; i < 512; i++) {
            float w = __ldg(wcol + (size_t)i * INP);
            unsigned long long wp = pk2(w, w);
            const unsigned long long* hp = (const unsigned long long*)(sh + i * BATCH);
            fma2(acc[0], hp[0], wp);
            fma2(acc[1], hp[1], wp);
            fma2(acc[2], hp[2], wp);
            fma2(acc[3], hp[3], wp);
            fma2(acc[4], hp[4], wp);
            fma2(acc[5], hp[5], wp);
            fma2(acc[6], hp[6], wp);
            fma2(acc[7], hp[7], wp);
        }
    }
    #pragma unroll
    for (int j = 0; j < 8; j++) {
        float lo, hi;
        upk2(acc[j], lo, hi);
        out[((size_t)(2 * j)     * SEQ + t) * INP + o] = lo;
        out[((size_t)(2 * j + 1) * SEQ + t) * INP + o] = hi;
    }
}

// ---------------- final hidden state h_T [l][b][i] ----------------
__global__ void k_ht(float* __restrict__ out) {
    int e = blockIdx.x * blockDim.x + threadIdx.x;
    if (e >= HT_ELEMS) return;
    int l = e / (BATCH * HID);
    int r = e % (BATCH * HID);
    int b = r / HID;
    int i = r % HID;
    float v;
    if (l == 0) v = g_h0[(SEQ - 1) & (HDEPTH - 1)][i * 16 + b];
    else        v = g_outsT[(size_t)(SEQ - 1) * (HID * BATCH) + i * 16 + b];
    out[(size_t)OUT_MAIN + e] = v;
}

// ---------------- launch ----------------
extern "C" void kernel_launch(void* const* d_in, const int* in_sizes, int n_in,
                              void* d_out, int out_size) {
    const float* x   = (const float*)d_in[0];
    const float* wih = (const float*)d_in[1];
    const float* whh = (const float*)d_in[2];
    const float* ow  = (const float*)d_in[3];
    const float* ob  = (const float*)d_in[4];
    float* out = (float*)d_out;

    k_zero_slots<<<1, 32>>>();
    k_xT<<<SEQ, 256>>>(x);
    k_csr<<<(3 * HID) / 8, 256>>>(wih, whh);
    k_wT<<<dim3(HID / 32, INP / 32), dim3(32, 32)>>>(ow);
    k_rnn<<<NCTA, NTHR>>>();
    k_proj<<<SEQ, NTHR>>>(ob, out);
    if (out_size >= OUT_MAIN + HT_ELEMS) {
        k_ht<<<(HT_ELEMS + 511) / 512, 512>>>(out);
    }
}